// round 1
// baseline (speedup 1.0000x reference)
#include <cuda_runtime.h>
#include <cstdint>

typedef unsigned long long u64;

// ---- packed f32x2 math (Blackwell sm_10x; ptxas never auto-generates these) ----
__device__ __forceinline__ u64 f2mul(u64 a, u64 b) {
    u64 d; asm("mul.rn.f32x2 %0, %1, %2;" : "=l"(d) : "l"(a), "l"(b)); return d;
}
__device__ __forceinline__ u64 f2add(u64 a, u64 b) {
    u64 d; asm("add.rn.f32x2 %0, %1, %2;" : "=l"(d) : "l"(a), "l"(b)); return d;
}
__device__ __forceinline__ u64 f2fma(u64 a, u64 b, u64 c) {
    u64 d; asm("fma.rn.f32x2 %0, %1, %2, %3;" : "=l"(d) : "l"(a), "l"(b), "l"(c)); return d;
}

// packed constants {v, v}
#define ONE2   0x3F8000003F800000ULL   // {1.0, 1.0}
#define NEG1_2 0xBF800000BF800000ULL   // {-1.0, -1.0}
#define HALF2  0x3F0000003F000000ULL   // {0.5, 0.5}
#define N8TH2  0xBE000000BE000000ULL   // {-0.125, -0.125}

// maj3 closed form: maj(a,b,c) = (a + b + c - a*b*c) / 2
//
// Scaled-tree trick: carry M = 2*maj between levels. For inputs that are
// already 2x true values (A=2a, B=2b, C=2c):
//   M_out = 2*maj(a,b,c) = (A+B+C)/2 - A*B*C/8 = A*(1/2 - B*C/8) + (B+C)/2
__device__ __forceinline__ u64 maj_scaled(u64 A, u64 B, u64 C) {
    u64 t = f2mul(B, C);
    u64 u = f2fma(t, N8TH2, HALF2);   // 1/2 - B*C/8
    u64 s = f2add(B, C);
    u64 v = f2mul(s, HALF2);          // (B+C)/2
    return f2fma(A, u, v);
}

// level-1: inputs are true-scale products a=w0*p0 etc; output M = 2*maj =
//   a + b + c - a*b*c = a*(1 - b*c) + (b + c)
__device__ __forceinline__ u64 maj_l1(u64 W0, u64 P0, u64 W1, u64 P1, u64 W2, u64 P2) {
    u64 a = f2mul(W0, P0);
    u64 b = f2mul(W1, P1);
    u64 c = f2mul(W2, P2);
    u64 t = f2mul(b, c);
    u64 u = f2fma(t, NEG1_2, ONE2);   // 1 - b*c
    u64 s = f2add(b, c);
    return f2fma(a, u, s);
}

// x: [8, 3, 64, 64]  weight: [64, 3, 3, 3]  out: [8, 64, 64, 64]
// Block = 256 threads = 64 w-lanes x 4 co-groups; grid = (64 rows, 4 batch pairs).
// Each lane packs batch images (n0, n0+1) into one f32x2.
__global__ void __launch_bounds__(256, 2)
sconv_maj_kernel(const float* __restrict__ x,
                 const float* __restrict__ wgt,
                 float* __restrict__ out)
{
    __shared__ float2 sP[3][3][66];   // [ch][row][col+1], batch-pair interleaved
    __shared__ float2 sW[64][28];     // duplicated weights {w, w}, padded row

    const int tid = threadIdx.x;
    const int h   = blockIdx.x;        // output row
    const int n0  = blockIdx.y * 2;    // batch pair

    // ---- stage input strip (rows h-1..h+1, cols -1..64, 3 ch, 2 batches) ----
    for (int idx = tid; idx < 3 * 3 * 66; idx += 256) {
        int c   = idx / 198;
        int rem = idx - c * 198;
        int r   = rem / 66;
        int col = rem - r * 66;
        int hh  = h - 1 + r;
        int ww  = col - 1;
        float2 v = make_float2(0.f, 0.f);
        if (hh >= 0 && hh < 64 && ww >= 0 && ww < 64) {
            int off = (c * 64 + hh) * 64 + ww;
            v.x = x[n0 * 12288 + off];
            v.y = x[n0 * 12288 + 12288 + off];
        }
        sP[c][r][col] = v;
    }
    // ---- duplicated weight table ----
    for (int idx = tid; idx < 64 * 27; idx += 256) {
        float w = wgt[idx];
        sW[idx / 27][idx % 27] = make_float2(w, w);
    }
    __syncthreads();

    const int w = tid & 63;    // pixel column
    const int g = tid >> 6;    // co-group 0..3

    // ---- load 27 packed patches into registers (reused for all 16 co) ----
    const u64* Pb = reinterpret_cast<const u64*>(&sP[0][0][0]);
    u64 P[27];
    #pragma unroll
    for (int q = 0; q < 9; ++q) {       // q = c*3 + r
        #pragma unroll
        for (int j = 0; j < 3; ++j)
            P[q * 3 + j] = Pb[q * 66 + w + j];
    }

    const u64* Wb = reinterpret_cast<const u64*>(&sW[0][0]);
    int ob = ((n0 * 64 + g) * 64 + h) * 64 + w;   // out index for co = g
    const u64* wr = Wb + g * 28;

    #pragma unroll 1
    for (int cc = 0; cc < 16; ++cc) {
        // ---- level 1 + 2 + 3 MAJ tree for this output channel ----
        u64 m2[3];
        #pragma unroll
        for (int ch = 0; ch < 3; ++ch) {
            u64 t0 = maj_l1(wr[ch*9 + 0], P[ch*9 + 0],
                            wr[ch*9 + 1], P[ch*9 + 1],
                            wr[ch*9 + 2], P[ch*9 + 2]);
            u64 t1 = maj_l1(wr[ch*9 + 3], P[ch*9 + 3],
                            wr[ch*9 + 4], P[ch*9 + 4],
                            wr[ch*9 + 5], P[ch*9 + 5]);
            u64 t2 = maj_l1(wr[ch*9 + 6], P[ch*9 + 6],
                            wr[ch*9 + 7], P[ch*9 + 7],
                            wr[ch*9 + 8], P[ch*9 + 8]);
            m2[ch] = maj_scaled(t0, t1, t2);
        }
        u64 m3  = maj_scaled(m2[0], m2[1], m2[2]);
        u64 res = f2mul(m3, HALF2);    // undo the 2x carry -> true maj

        float2 rf;
        asm("mov.b64 {%0, %1}, %2;" : "=f"(rf.x), "=f"(rf.y) : "l"(res));
        out[ob]          = rf.x;       // batch n0
        out[ob + 262144] = rf.y;       // batch n0+1  (64*64*64 floats)

        ob += 4 * 4096;                // co += 4
        wr += 4 * 28;
    }
}

extern "C" void kernel_launch(void* const* d_in, const int* in_sizes, int n_in,
                              void* d_out, int out_size)
{
    const float* x   = (const float*)d_in[0];   // [8,3,64,64]
    const float* wgt = (const float*)d_in[1];   // [64,3,3,3]
    float* out = (float*)d_out;                 // [8,64,64,64]

    dim3 grid(64, 4);   // 64 output rows x 4 batch pairs
    sconv_maj_kernel<<<grid, 256>>>(x, wgt, out);
}